// round 5
// baseline (speedup 1.0000x reference)
#include <cuda_runtime.h>

// Bilateral 5x5, sigma_color = sigma_space = 1.1, reflect pad, (16,3,512,512) f32.
//
// out = sum_k w_k*s_k*p_k / sum_k w_k*s_k,  w_k = exp(-a*diff^2), a = 1/(2*1.1^2);
// the reference's two normalizations cancel. exp(-a*u), u in [0,1], is a deg-2
// Chebyshev poly (end-to-end rel_err ~6e-5). Horizontal spatial weight folded
// into the poly coefficients (3 sets); vertical weight applied per row.
//
// R5: vertical 2-pixel blocking — each thread computes a 2x2 output quad.
// 6 smem rows loaded once feed both pixel rows (independent accumulator
// chains -> 2x ILP); zero epilogue (2 accumulators per pixel-pair).

#define H 512
#define W 512
#define NPLANES 48

#define TILE_W 64
#define TILE_H 16
#define BLK_X 32
#define BLK_Y 8
#define SM_W  68
#define SM_H  20
#define SM_N  (SM_H * SM_W)

// 1D spatial gaussian exp(-a*d^2), d in {1,2}
#define G1f 0.66151464f
#define G2f 0.19149516f

// deg-2 Chebyshev coeffs for exp(-a*u), u in [0,1]
#define Q0 0.99969391f
#define Q1 -0.40757903f
#define Q2 0.06969310f

typedef unsigned long long u64;

__device__ __forceinline__ u64 pk(float lo, float hi) {
    u64 r; asm("mov.b64 %0, {%1, %2};" : "=l"(r) : "f"(lo), "f"(hi)); return r;
}
__device__ __forceinline__ u64 f2add(u64 a, u64 b) {
    u64 d; asm("add.rn.f32x2 %0, %1, %2;" : "=l"(d) : "l"(a), "l"(b)); return d;
}
__device__ __forceinline__ u64 f2sub(u64 a, u64 b) {
    u64 d; asm("sub.rn.f32x2 %0, %1, %2;" : "=l"(d) : "l"(a), "l"(b)); return d;
}
__device__ __forceinline__ u64 f2mul(u64 a, u64 b) {
    u64 d; asm("mul.rn.f32x2 %0, %1, %2;" : "=l"(d) : "l"(a), "l"(b)); return d;
}
__device__ __forceinline__ u64 f2fma(u64 a, u64 b, u64 c) {
    u64 d; asm("fma.rn.f32x2 %0, %1, %2, %3;" : "=l"(d) : "l"(a), "l"(b), "l"(c)); return d;
}
__device__ __forceinline__ void unpk(u64 q, float& lo, float& hi) {
    asm("mov.b64 {%0, %1}, %2;" : "=f"(lo), "=f"(hi) : "l"(q));
}

__device__ __forceinline__ int reflect_idx(int i, int n) {
    if (i < 0)  i = -i;
    if (i >= n) i = 2 * n - 2 - i;
    return i;
}

__global__ __launch_bounds__(BLK_X * BLK_Y, 4)
void bilateral_kernel(const float* __restrict__ in, float* __restrict__ out) {
    // smB[r][c] == smA[r][c+1]  (shifted copy -> odd-offset pairs are aligned LDS.64)
    __shared__ __align__(8) float smA[SM_H][SM_W];
    __shared__ __align__(8) float smB[SM_H][SM_W];

    const int tx = threadIdx.x;
    const int ty = threadIdx.y;
    const int bx = blockIdx.x * TILE_W;
    const int by = blockIdx.y * TILE_H;
    const long pbase = (long)blockIdx.z * (H * W);

    // ---- cooperative tile load (reflect only on border blocks) ----
    const int t = ty * BLK_X + tx;
    const bool interior = (bx != 0) && (bx != (W - TILE_W)) &&
                          (by != 0) && (by != (H - TILE_H));
    if (interior) {
        const float* src = in + pbase + (long)(by - 2) * W + (bx - 2);
        #pragma unroll
        for (int idx = 0; idx < SM_N; idx += BLK_X * BLK_Y) {
            int i = idx + t;
            if (i < SM_N) {
                int r = i / SM_W;
                int c = i - r * SM_W;
                float v = src[r * W + c];
                smA[r][c] = v;
                if (c > 0) smB[r][c - 1] = v;
            }
        }
    } else {
        #pragma unroll
        for (int idx = 0; idx < SM_N; idx += BLK_X * BLK_Y) {
            int i = idx + t;
            if (i < SM_N) {
                int r = i / SM_W;
                int c = i - r * SM_W;
                int gy = reflect_idx(by - 2 + r, H);
                int gx = reflect_idx(bx - 2 + c, W);
                float v = in[pbase + gy * W + gx];
                smA[r][c] = v;
                if (c > 0) smB[r][c - 1] = v;
            }
        }
    }
    __syncthreads();

    // horizontally-folded poly coefficient sets: coef = g * {Q2, Q1, Q0}
    const u64 A2 = pk(Q2, Q2);                          // g = 1
    const u64 A1 = pk(Q1, Q1);
    const u64 A0 = pk(Q0, Q0);
    const u64 B2 = pk(0.04610273f, 0.04610273f);        // g = G1
    const u64 B1 = pk(-0.26961989f, -0.26961989f);
    const u64 B0 = pk(0.66131215f, 0.66131215f);
    const u64 E2 = pk(0.01334589f, 0.01334589f);        // g = G2
    const u64 E1 = pk(-0.07804951f, -0.07804951f);
    const u64 E0 = pk(0.19143654f, 0.19143654f);
    const u64 GV1 = pk(G1f, G1f);
    const u64 GV2 = pk(G2f, G2f);

    const int col = 2 * tx;
    const int rb  = 2 * ty;     // smem row of pixel-A's top halo row

    const u64 ctrA = *(const u64*)&smA[rb + 2][col + 2];
    const u64 ctrB = *(const u64*)&smA[rb + 3][col + 2];

    u64 numA = 0ull, denA = 0ull, numB = 0ull, denB = 0ull;

    // one 5-tap row against a given center, horizontal weights folded in
    #define TAP(P, K2, K1, K0)                          \
    {                                                   \
        u64 dd = f2sub((P), ctr);                       \
        u64 uu = f2mul(dd, dd);                         \
        u64 tt = f2fma((K2), uu, (K1));                 \
        u64 ww = f2fma(tt, uu, (K0));                   \
        rd = f2add(rd, ww);                             \
        rn = f2fma(ww, (P), rn);                        \
    }

    #define ROWACC(CTR, NUM, DEN, GV, UNIT)             \
    {                                                   \
        u64 ctr = (CTR);                                \
        u64 rn = 0ull, rd = 0ull;                       \
        TAP(p0, E2, E1, E0)                             \
        TAP(p1, B2, B1, B0)                             \
        TAP(p2, A2, A1, A0)                             \
        TAP(p3, B2, B1, B0)                             \
        TAP(p4, E2, E1, E0)                             \
        if (UNIT) { DEN = f2add(DEN, rd); NUM = f2add(NUM, rn); }  \
        else      { DEN = f2fma((GV), rd, DEN); NUM = f2fma((GV), rn, NUM); } \
    }

    #define ROWLOAD(r)                                  \
        const float* rA = &smA[rb + (r)][col];          \
        const float* rB = &smB[rb + (r)][col];          \
        u64 p0 = *(const u64*)(rA + 0);                 \
        u64 p1 = *(const u64*)(rB + 0);                 \
        u64 p2 = *(const u64*)(rA + 2);                 \
        u64 p3 = *(const u64*)(rB + 2);                 \
        u64 p4 = *(const u64*)(rA + 4);

    { ROWLOAD(0) ROWACC(ctrA, numA, denA, GV2, false) }
    { ROWLOAD(1) ROWACC(ctrA, numA, denA, GV1, false)
                 ROWACC(ctrB, numB, denB, GV2, false) }
    { ROWLOAD(2) ROWACC(ctrA, numA, denA, GV1, true)   // weight 1
                 ROWACC(ctrB, numB, denB, GV1, false) }
    { ROWLOAD(3) ROWACC(ctrA, numA, denA, GV1, false)
                 ROWACC(ctrB, numB, denB, GV1, true) }  // weight 1
    { ROWLOAD(4) ROWACC(ctrA, numA, denA, GV2, false)
                 ROWACC(ctrB, numB, denB, GV1, false) }
    { ROWLOAD(5) ROWACC(ctrB, numB, denB, GV2, false) }

    #undef TAP
    #undef ROWACC
    #undef ROWLOAD

    float na0, na1, da0, da1, nb0, nb1, db0, db1;
    unpk(numA, na0, na1);
    unpk(denA, da0, da1);
    unpk(numB, nb0, nb1);
    unpk(denB, db0, db1);

    float2 oA, oB;
    oA.x = __fdividef(na0, da0);
    oA.y = __fdividef(na1, da1);
    oB.x = __fdividef(nb0, db0);
    oB.y = __fdividef(nb1, db1);

    const int gy = by + rb;
    float* op = out + pbase + (long)gy * W + bx + col;
    *(float2*)op       = oA;
    *(float2*)(op + W) = oB;
}

extern "C" void kernel_launch(void* const* d_in, const int* in_sizes, int n_in,
                              void* d_out, int out_size) {
    const float* x = (const float*)d_in[0];
    float* y = (float*)d_out;
    dim3 block(BLK_X, BLK_Y);
    dim3 grid(W / TILE_W, H / TILE_H, NPLANES);
    bilateral_kernel<<<grid, block>>>(x, y);
}

// round 6
// speedup vs baseline: 1.1037x; 1.1037x over previous
#include <cuda_runtime.h>

// Bilateral 5x5, sigma_color = sigma_space = 1.1, reflect pad, (16,3,512,512) f32.
//
// out = sum_k w_k*s_k*p_k / sum_k w_k*s_k,  w_k = exp(-a*diff^2), a = 1/(2*1.1^2);
// the reference's two normalizations cancel. exp(-a*u), u in [0,1], is a deg-2
// Chebyshev poly. Horizontal spatial weight folded into the poly coefficients
// (3 sets); vertical weight applied once per row. Zero epilogue.
//
// R6: R4 geometry (2 px/thread, 64x8 tiles) + folded coefficients (2
// accumulators, no epilogue) + launch_bounds(256,6) occupancy floor.

#define H 512
#define W 512
#define NPLANES 48

#define TILE_W 64
#define TILE_H 8
#define BLK_X 32
#define BLK_Y 8
#define SM_W  68
#define SM_H  12
#define SM_N  (SM_H * SM_W)

#define G1f 0.66151464f
#define G2f 0.19149516f

// deg-2 Chebyshev coeffs for exp(-a*u), u in [0,1]
#define Q0 0.99969391f
#define Q1 -0.40757903f
#define Q2 0.06969310f

typedef unsigned long long u64;

__device__ __forceinline__ u64 pk(float lo, float hi) {
    u64 r; asm("mov.b64 %0, {%1, %2};" : "=l"(r) : "f"(lo), "f"(hi)); return r;
}
__device__ __forceinline__ u64 f2add(u64 a, u64 b) {
    u64 d; asm("add.rn.f32x2 %0, %1, %2;" : "=l"(d) : "l"(a), "l"(b)); return d;
}
__device__ __forceinline__ u64 f2sub(u64 a, u64 b) {
    u64 d; asm("sub.rn.f32x2 %0, %1, %2;" : "=l"(d) : "l"(a), "l"(b)); return d;
}
__device__ __forceinline__ u64 f2mul(u64 a, u64 b) {
    u64 d; asm("mul.rn.f32x2 %0, %1, %2;" : "=l"(d) : "l"(a), "l"(b)); return d;
}
__device__ __forceinline__ u64 f2fma(u64 a, u64 b, u64 c) {
    u64 d; asm("fma.rn.f32x2 %0, %1, %2, %3;" : "=l"(d) : "l"(a), "l"(b), "l"(c)); return d;
}
__device__ __forceinline__ void unpk(u64 q, float& lo, float& hi) {
    asm("mov.b64 {%0, %1}, %2;" : "=f"(lo), "=f"(hi) : "l"(q));
}

__device__ __forceinline__ int reflect_idx(int i, int n) {
    if (i < 0)  i = -i;
    if (i >= n) i = 2 * n - 2 - i;
    return i;
}

__global__ __launch_bounds__(BLK_X * BLK_Y, 6)
void bilateral_kernel(const float* __restrict__ in, float* __restrict__ out) {
    // smB[r][c] == smA[r][c+1]  (shifted copy -> odd-offset pairs are aligned LDS.64)
    __shared__ __align__(8) float smA[SM_H][SM_W];
    __shared__ __align__(8) float smB[SM_H][SM_W];

    const int tx = threadIdx.x;
    const int ty = threadIdx.y;
    const int bx = blockIdx.x * TILE_W;
    const int by = blockIdx.y * TILE_H;
    const long pbase = (long)blockIdx.z * (H * W);

    // ---- cooperative tile load (reflect math only on border blocks) ----
    const int t = ty * BLK_X + tx;
    const bool interior = (bx != 0) && (bx != (W - TILE_W)) &&
                          (by != 0) && (by != (H - TILE_H));
    if (interior) {
        const float* src = in + pbase + (long)(by - 2) * W + (bx - 2);
        #pragma unroll
        for (int idx = 0; idx < SM_N; idx += BLK_X * BLK_Y) {
            int i = idx + t;
            if (i < SM_N) {
                int r = i / SM_W;
                int c = i - r * SM_W;
                float v = src[r * W + c];
                smA[r][c] = v;
                if (c > 0) smB[r][c - 1] = v;
            }
        }
    } else {
        #pragma unroll
        for (int idx = 0; idx < SM_N; idx += BLK_X * BLK_Y) {
            int i = idx + t;
            if (i < SM_N) {
                int r = i / SM_W;
                int c = i - r * SM_W;
                int gy = reflect_idx(by - 2 + r, H);
                int gx = reflect_idx(bx - 2 + c, W);
                float v = in[pbase + gy * W + gx];
                smA[r][c] = v;
                if (c > 0) smB[r][c - 1] = v;
            }
        }
    }
    __syncthreads();

    // horizontally-folded poly coefficient sets: coef = g * {Q2, Q1, Q0}
    const u64 A2 = pk(Q2, Q2);                          // g = 1
    const u64 A1 = pk(Q1, Q1);
    const u64 A0 = pk(Q0, Q0);
    const u64 B2 = pk(0.04610273f, 0.04610273f);        // g = G1
    const u64 B1 = pk(-0.26961989f, -0.26961989f);
    const u64 B0 = pk(0.66131215f, 0.66131215f);
    const u64 E2 = pk(0.01334589f, 0.01334589f);        // g = G2
    const u64 E1 = pk(-0.07804951f, -0.07804951f);
    const u64 E0 = pk(0.19143654f, 0.19143654f);
    const u64 GV1 = pk(G1f, G1f);
    const u64 GV2 = pk(G2f, G2f);

    const int col = 2 * tx;
    const u64 ctr = *(const u64*)&smA[ty + 2][col + 2];

    u64 num = 0ull, den = 0ull;

    #define TAP(P, K2, K1, K0)                          \
    {                                                   \
        u64 dd = f2sub((P), ctr);                       \
        u64 uu = f2mul(dd, dd);                         \
        u64 tt = f2fma((K2), uu, (K1));                 \
        u64 ww = f2fma(tt, uu, (K0));                   \
        rd = f2add(rd, ww);                             \
        rn = f2fma(ww, (P), rn);                        \
    }

    #define ROWDO(r, GV, UNIT)                          \
    {                                                   \
        const float* rA = &smA[ty + (r)][col];          \
        const float* rB = &smB[ty + (r)][col];          \
        u64 p0 = *(const u64*)(rA + 0);                 \
        u64 p1 = *(const u64*)(rB + 0);                 \
        u64 p2 = *(const u64*)(rA + 2);                 \
        u64 p3 = *(const u64*)(rB + 2);                 \
        u64 p4 = *(const u64*)(rA + 4);                 \
        u64 rn = 0ull, rd = 0ull;                       \
        TAP(p0, E2, E1, E0)                             \
        TAP(p1, B2, B1, B0)                             \
        TAP(p2, A2, A1, A0)                             \
        TAP(p3, B2, B1, B0)                             \
        TAP(p4, E2, E1, E0)                             \
        if (UNIT) { den = f2add(den, rd); num = f2add(num, rn); }             \
        else      { den = f2fma((GV), rd, den); num = f2fma((GV), rn, num); } \
    }

    ROWDO(0, GV2, false)
    ROWDO(1, GV1, false)
    ROWDO(2, GV1, true)     // center row: vertical weight 1
    ROWDO(3, GV1, false)
    ROWDO(4, GV2, false)

    #undef TAP
    #undef ROWDO

    float n0, n1, d0, d1;
    unpk(num, n0, n1);
    unpk(den, d0, d1);
    float2 o;
    o.x = __fdividef(n0, d0);
    o.y = __fdividef(n1, d1);
    *(float2*)&out[pbase + (by + ty) * W + bx + col] = o;
}

extern "C" void kernel_launch(void* const* d_in, const int* in_sizes, int n_in,
                              void* d_out, int out_size) {
    const float* x = (const float*)d_in[0];
    float* y = (float*)d_out;
    dim3 block(BLK_X, BLK_Y);
    dim3 grid(W / TILE_W, H / TILE_H, NPLANES);
    bilateral_kernel<<<grid, block>>>(x, y);
}

// round 7
// speedup vs baseline: 1.2161x; 1.1018x over previous
#include <cuda_runtime.h>

// Bilateral 5x5, sigma_color = sigma_space = 1.1, reflect pad, (16,3,512,512) f32.
//
// out = sum_k w_k*s_k*p_k / sum_k w_k*s_k,  w_k = exp(-a*diff^2), a = 1/(2*1.1^2);
// the reference's two normalizations cancel. exp(-a*u), u in [0,1], is a deg-2
// Chebyshev poly. Horizontal spatial weight folded into the poly coefficients
// (3 sets); vertical weight applied once per row (center row direct).
//
// R7: division-free tile loader (no i/68, i%68 IMAD chains); center row
// accumulates directly into num/den (no combine, no zero-init).

#define H 512
#define W 512
#define NPLANES 48

#define TILE_W 64
#define TILE_H 8
#define BLK_X 32
#define BLK_Y 8
#define SM_W  68
#define SM_H  12

#define G1f 0.66151464f
#define G2f 0.19149516f

// deg-2 Chebyshev coeffs for exp(-a*u), u in [0,1]
#define Q0 0.99969391f
#define Q1 -0.40757903f
#define Q2 0.06969310f

typedef unsigned long long u64;

__device__ __forceinline__ u64 pk(float lo, float hi) {
    u64 r; asm("mov.b64 %0, {%1, %2};" : "=l"(r) : "f"(lo), "f"(hi)); return r;
}
__device__ __forceinline__ u64 f2add(u64 a, u64 b) {
    u64 d; asm("add.rn.f32x2 %0, %1, %2;" : "=l"(d) : "l"(a), "l"(b)); return d;
}
__device__ __forceinline__ u64 f2sub(u64 a, u64 b) {
    u64 d; asm("sub.rn.f32x2 %0, %1, %2;" : "=l"(d) : "l"(a), "l"(b)); return d;
}
__device__ __forceinline__ u64 f2mul(u64 a, u64 b) {
    u64 d; asm("mul.rn.f32x2 %0, %1, %2;" : "=l"(d) : "l"(a), "l"(b)); return d;
}
__device__ __forceinline__ u64 f2fma(u64 a, u64 b, u64 c) {
    u64 d; asm("fma.rn.f32x2 %0, %1, %2, %3;" : "=l"(d) : "l"(a), "l"(b), "l"(c)); return d;
}
__device__ __forceinline__ void unpk(u64 q, float& lo, float& hi) {
    asm("mov.b64 {%0, %1}, %2;" : "=f"(lo), "=f"(hi) : "l"(q));
}

__device__ __forceinline__ int reflect_idx(int i, int n) {
    if (i < 0)  i = -i;
    if (i >= n) i = 2 * n - 2 - i;
    return i;
}

__global__ __launch_bounds__(BLK_X * BLK_Y, 6)
void bilateral_kernel(const float* __restrict__ in, float* __restrict__ out) {
    // smB[r][c] == smA[r][c+1]  (shifted copy -> odd-offset pairs are aligned LDS.64)
    __shared__ __align__(8) float smA[SM_H][SM_W];
    __shared__ __align__(8) float smB[SM_H][SM_W];

    const int tx = threadIdx.x;
    const int ty = threadIdx.y;
    const int bx = blockIdx.x * TILE_W;
    const int by = blockIdx.y * TILE_H;
    const long pbase = (long)blockIdx.z * (H * W);

    // ---- division-free cooperative tile load ----
    const bool interior = (bx != 0) && (bx != (W - TILE_W)) &&
                          (by != 0) && (by != (H - TILE_H));

    #define STORE_SM(r, c, v)                  \
    {                                          \
        smA[r][c] = (v);                       \
        if ((c) > 0) smB[r][(c) - 1] = (v);    \
    }

    if (interior) {
        const float* src = in + pbase + (long)(by - 2) * W + (bx - 2);
        #pragma unroll
        for (int rr = 0; rr < 2; rr++) {
            int r = ty + rr * BLK_Y;
            if (r < SM_H) {
                const float* sr = src + (long)r * W;
                #pragma unroll
                for (int cc = 0; cc < 3; cc++) {
                    int c = tx + cc * BLK_X;
                    if (c < SM_W) {
                        float v = sr[c];
                        STORE_SM(r, c, v)
                    }
                }
            }
        }
    } else {
        #pragma unroll
        for (int rr = 0; rr < 2; rr++) {
            int r = ty + rr * BLK_Y;
            if (r < SM_H) {
                int gy = reflect_idx(by - 2 + r, H);
                const float* sr = in + pbase + (long)gy * W;
                #pragma unroll
                for (int cc = 0; cc < 3; cc++) {
                    int c = tx + cc * BLK_X;
                    if (c < SM_W) {
                        int gx = reflect_idx(bx - 2 + c, W);
                        float v = sr[gx];
                        STORE_SM(r, c, v)
                    }
                }
            }
        }
    }
    #undef STORE_SM
    __syncthreads();

    // horizontally-folded poly coefficient sets: coef = g * {Q2, Q1, Q0}
    const u64 A2 = pk(Q2, Q2);                          // g = 1
    const u64 A1 = pk(Q1, Q1);
    const u64 A0 = pk(Q0, Q0);
    const u64 B2 = pk(0.04610273f, 0.04610273f);        // g = G1
    const u64 B1 = pk(-0.26961989f, -0.26961989f);
    const u64 B0 = pk(0.66131215f, 0.66131215f);
    const u64 E2 = pk(0.01334589f, 0.01334589f);        // g = G2
    const u64 E1 = pk(-0.07804951f, -0.07804951f);
    const u64 E0 = pk(0.19143654f, 0.19143654f);
    const u64 GV1 = pk(G1f, G1f);
    const u64 GV2 = pk(G2f, G2f);

    const int col = 2 * tx;
    const u64 ctr = *(const u64*)&smA[ty + 2][col + 2];

    u64 num, den;

    #define ROWLOAD(r)                                  \
        const float* rA = &smA[ty + (r)][col];          \
        const float* rB = &smB[ty + (r)][col];          \
        u64 p0 = *(const u64*)(rA + 0);                 \
        u64 p1 = *(const u64*)(rB + 0);                 \
        u64 p2 = *(const u64*)(rA + 2);                 \
        u64 p3 = *(const u64*)(rB + 2);                 \
        u64 p4 = *(const u64*)(rA + 4);

    // tap producing weight only
    #define TAPW(P, K2, K1, K0, WOUT)                   \
        u64 WOUT;                                       \
        {                                               \
            u64 dd = f2sub((P), ctr);                   \
            u64 uu = f2mul(dd, dd);                     \
            u64 tt = f2fma((K2), uu, (K1));             \
            WOUT = f2fma(tt, uu, (K0));                 \
        }

    // ---- center row first: direct init of num/den ----
    {
        ROWLOAD(2)
        TAPW(p0, E2, E1, E0, w0)
        den = w0;
        num = f2mul(w0, p0);
        TAPW(p1, B2, B1, B0, w1)
        den = f2add(den, w1);
        num = f2fma(w1, p1, num);
        TAPW(p2, A2, A1, A0, w2)
        den = f2add(den, w2);
        num = f2fma(w2, p2, num);
        TAPW(p3, B2, B1, B0, w3)
        den = f2add(den, w3);
        num = f2fma(w3, p3, num);
        TAPW(p4, E2, E1, E0, w4)
        den = f2add(den, w4);
        num = f2fma(w4, p4, num);
    }

    // ---- off-center rows: row temps + vertical-weight combine ----
    #define ROWDO(r, GV)                                \
    {                                                   \
        ROWLOAD(r)                                      \
        TAPW(p0, E2, E1, E0, w0)                        \
        u64 rd = w0;                                    \
        u64 rn = f2mul(w0, p0);                         \
        TAPW(p1, B2, B1, B0, w1)                        \
        rd = f2add(rd, w1);                             \
        rn = f2fma(w1, p1, rn);                         \
        TAPW(p2, A2, A1, A0, w2)                        \
        rd = f2add(rd, w2);                             \
        rn = f2fma(w2, p2, rn);                         \
        TAPW(p3, B2, B1, B0, w3)                        \
        rd = f2add(rd, w3);                             \
        rn = f2fma(w3, p3, rn);                         \
        TAPW(p4, E2, E1, E0, w4)                        \
        rd = f2add(rd, w4);                             \
        rn = f2fma(w4, p4, rn);                         \
        den = f2fma((GV), rd, den);                     \
        num = f2fma((GV), rn, num);                     \
    }

    ROWDO(0, GV2)
    ROWDO(1, GV1)
    ROWDO(3, GV1)
    ROWDO(4, GV2)

    #undef ROWDO
    #undef TAPW
    #undef ROWLOAD

    float n0, n1, d0, d1;
    unpk(num, n0, n1);
    unpk(den, d0, d1);
    float2 o;
    o.x = __fdividef(n0, d0);
    o.y = __fdividef(n1, d1);
    *(float2*)&out[pbase + (by + ty) * W + bx + col] = o;
}

extern "C" void kernel_launch(void* const* d_in, const int* in_sizes, int n_in,
                              void* d_out, int out_size) {
    const float* x = (const float*)d_in[0];
    float* y = (float*)d_out;
    dim3 block(BLK_X, BLK_Y);
    dim3 grid(W / TILE_W, H / TILE_H, NPLANES);
    bilateral_kernel<<<grid, block>>>(x, y);
}

// round 8
// speedup vs baseline: 1.3307x; 1.0943x over previous
#include <cuda_runtime.h>

// Bilateral 5x5, sigma_color = sigma_space = 1.1, reflect pad, (16,3,512,512) f32.
//
// out = sum_k w_k*s_k*p_k / sum_k w_k*s_k,  w_k = exp(-a*diff^2), a = 1/(2*1.1^2);
// the reference's two normalizations cancel. exp(-a*u), u in [0,1], is a deg-2
// Chebyshev poly. Horizontal spatial weight folded into the poly coefficients
// (3 sets); vertical weight applied once per row (center row direct).
//
// R8: 32-bit indexing everywhere (tensor = 12.6M elems < 2^31) and
// launch_bounds(256,7) -> 36-reg cap, 87.5% theoretical occupancy.

#define H 512
#define W 512
#define NPLANES 48

#define TILE_W 64
#define TILE_H 8
#define BLK_X 32
#define BLK_Y 8
#define SM_W  68
#define SM_H  12

#define G1f 0.66151464f
#define G2f 0.19149516f

// deg-2 Chebyshev coeffs for exp(-a*u), u in [0,1]
#define Q0 0.99969391f
#define Q1 -0.40757903f
#define Q2 0.06969310f

typedef unsigned long long u64;

__device__ __forceinline__ u64 pk(float lo, float hi) {
    u64 r; asm("mov.b64 %0, {%1, %2};" : "=l"(r) : "f"(lo), "f"(hi)); return r;
}
__device__ __forceinline__ u64 f2add(u64 a, u64 b) {
    u64 d; asm("add.rn.f32x2 %0, %1, %2;" : "=l"(d) : "l"(a), "l"(b)); return d;
}
__device__ __forceinline__ u64 f2sub(u64 a, u64 b) {
    u64 d; asm("sub.rn.f32x2 %0, %1, %2;" : "=l"(d) : "l"(a), "l"(b)); return d;
}
__device__ __forceinline__ u64 f2mul(u64 a, u64 b) {
    u64 d; asm("mul.rn.f32x2 %0, %1, %2;" : "=l"(d) : "l"(a), "l"(b)); return d;
}
__device__ __forceinline__ u64 f2fma(u64 a, u64 b, u64 c) {
    u64 d; asm("fma.rn.f32x2 %0, %1, %2, %3;" : "=l"(d) : "l"(a), "l"(b), "l"(c)); return d;
}
__device__ __forceinline__ void unpk(u64 q, float& lo, float& hi) {
    asm("mov.b64 {%0, %1}, %2;" : "=f"(lo), "=f"(hi) : "l"(q));
}

__device__ __forceinline__ int reflect_idx(int i, int n) {
    if (i < 0)  i = -i;
    if (i >= n) i = 2 * n - 2 - i;
    return i;
}

__global__ __launch_bounds__(BLK_X * BLK_Y, 7)
void bilateral_kernel(const float* __restrict__ in, float* __restrict__ out) {
    // smB[r][c] == smA[r][c+1]  (shifted copy -> odd-offset pairs are aligned LDS.64)
    __shared__ __align__(8) float smA[SM_H][SM_W];
    __shared__ __align__(8) float smB[SM_H][SM_W];

    const int tx = threadIdx.x;
    const int ty = threadIdx.y;
    const int bx = blockIdx.x * TILE_W;
    const int by = blockIdx.y * TILE_H;
    const int pbase = blockIdx.z * (H * W);    // < 2^31, 32-bit safe

    // ---- division-free cooperative tile load (32-bit indexing) ----
    const bool interior = (bx != 0) && (bx != (W - TILE_W)) &&
                          (by != 0) && (by != (H - TILE_H));

    #define STORE_SM(r, c, v)                  \
    {                                          \
        smA[r][c] = (v);                       \
        if ((c) > 0) smB[r][(c) - 1] = (v);    \
    }

    if (interior) {
        const float* src = in + (pbase + (by - 2) * W + (bx - 2));
        #pragma unroll
        for (int rr = 0; rr < 2; rr++) {
            int r = ty + rr * BLK_Y;
            if (r < SM_H) {
                const float* sr = src + r * W;
                #pragma unroll
                for (int cc = 0; cc < 3; cc++) {
                    int c = tx + cc * BLK_X;
                    if (c < SM_W) {
                        float v = sr[c];
                        STORE_SM(r, c, v)
                    }
                }
            }
        }
    } else {
        #pragma unroll
        for (int rr = 0; rr < 2; rr++) {
            int r = ty + rr * BLK_Y;
            if (r < SM_H) {
                int gy = reflect_idx(by - 2 + r, H);
                const float* sr = in + (pbase + gy * W);
                #pragma unroll
                for (int cc = 0; cc < 3; cc++) {
                    int c = tx + cc * BLK_X;
                    if (c < SM_W) {
                        int gx = reflect_idx(bx - 2 + c, W);
                        float v = sr[gx];
                        STORE_SM(r, c, v)
                    }
                }
            }
        }
    }
    #undef STORE_SM
    __syncthreads();

    // horizontally-folded poly coefficient sets: coef = g * {Q2, Q1, Q0}
    const u64 A2 = pk(Q2, Q2);                          // g = 1
    const u64 A1 = pk(Q1, Q1);
    const u64 A0 = pk(Q0, Q0);
    const u64 B2 = pk(0.04610273f, 0.04610273f);        // g = G1
    const u64 B1 = pk(-0.26961989f, -0.26961989f);
    const u64 B0 = pk(0.66131215f, 0.66131215f);
    const u64 E2 = pk(0.01334589f, 0.01334589f);        // g = G2
    const u64 E1 = pk(-0.07804951f, -0.07804951f);
    const u64 E0 = pk(0.19143654f, 0.19143654f);
    const u64 GV1 = pk(G1f, G1f);
    const u64 GV2 = pk(G2f, G2f);

    const int col = 2 * tx;
    const u64 ctr = *(const u64*)&smA[ty + 2][col + 2];

    u64 num, den;

    #define ROWLOAD(r)                                  \
        const float* rA = &smA[ty + (r)][col];          \
        const float* rB = &smB[ty + (r)][col];          \
        u64 p0 = *(const u64*)(rA + 0);                 \
        u64 p1 = *(const u64*)(rB + 0);                 \
        u64 p2 = *(const u64*)(rA + 2);                 \
        u64 p3 = *(const u64*)(rB + 2);                 \
        u64 p4 = *(const u64*)(rA + 4);

    #define TAPW(P, K2, K1, K0, WOUT)                   \
        u64 WOUT;                                       \
        {                                               \
            u64 dd = f2sub((P), ctr);                   \
            u64 uu = f2mul(dd, dd);                     \
            u64 tt = f2fma((K2), uu, (K1));             \
            WOUT = f2fma(tt, uu, (K0));                 \
        }

    // ---- center row first: direct init of num/den ----
    {
        ROWLOAD(2)
        TAPW(p0, E2, E1, E0, w0)
        den = w0;
        num = f2mul(w0, p0);
        TAPW(p1, B2, B1, B0, w1)
        den = f2add(den, w1);
        num = f2fma(w1, p1, num);
        TAPW(p2, A2, A1, A0, w2)
        den = f2add(den, w2);
        num = f2fma(w2, p2, num);
        TAPW(p3, B2, B1, B0, w3)
        den = f2add(den, w3);
        num = f2fma(w3, p3, num);
        TAPW(p4, E2, E1, E0, w4)
        den = f2add(den, w4);
        num = f2fma(w4, p4, num);
    }

    // ---- off-center rows: row temps + vertical-weight combine ----
    #define ROWDO(r, GV)                                \
    {                                                   \
        ROWLOAD(r)                                      \
        TAPW(p0, E2, E1, E0, w0)                        \
        u64 rd = w0;                                    \
        u64 rn = f2mul(w0, p0);                         \
        TAPW(p1, B2, B1, B0, w1)                        \
        rd = f2add(rd, w1);                             \
        rn = f2fma(w1, p1, rn);                         \
        TAPW(p2, A2, A1, A0, w2)                        \
        rd = f2add(rd, w2);                             \
        rn = f2fma(w2, p2, rn);                         \
        TAPW(p3, B2, B1, B0, w3)                        \
        rd = f2add(rd, w3);                             \
        rn = f2fma(w3, p3, rn);                         \
        TAPW(p4, E2, E1, E0, w4)                        \
        rd = f2add(rd, w4);                             \
        rn = f2fma(w4, p4, rn);                         \
        den = f2fma((GV), rd, den);                     \
        num = f2fma((GV), rn, num);                     \
    }

    ROWDO(0, GV2)
    ROWDO(1, GV1)
    ROWDO(3, GV1)
    ROWDO(4, GV2)

    #undef ROWDO
    #undef TAPW
    #undef ROWLOAD

    float n0, n1, d0, d1;
    unpk(num, n0, n1);
    unpk(den, d0, d1);
    float2 o;
    o.x = __fdividef(n0, d0);
    o.y = __fdividef(n1, d1);
    *(float2*)&out[pbase + (by + ty) * W + bx + col] = o;
}

extern "C" void kernel_launch(void* const* d_in, const int* in_sizes, int n_in,
                              void* d_out, int out_size) {
    const float* x = (const float*)d_in[0];
    float* y = (float*)d_out;
    dim3 block(BLK_X, BLK_Y);
    dim3 grid(W / TILE_W, H / TILE_H, NPLANES);
    bilateral_kernel<<<grid, block>>>(x, y);
}

// round 9
// speedup vs baseline: 1.4937x; 1.1224x over previous
#include <cuda_runtime.h>

// Bilateral 5x5, sigma_color = sigma_space = 1.1, reflect pad, (16,3,512,512) f32.
//
// out = sum_k w_k*s_k*p_k / sum_k w_k*s_k,  w_k = exp(-a*diff^2), a = 1/(2*1.1^2);
// the reference's two normalizations cancel. exp(-a*u), u in [0,1], is a deg-2
// Chebyshev poly. Horizontal spatial weight folded into the poly coefficients
// (3 sets); vertical weight applied once per row; accumulators init from the
// first row (no zero-init).
//
// R9: 2x2 output quad per thread (lean R8 body + vertical blocking): 6 shared
// rows feed both pixel rows -> 30 row-LDS per quad vs 50, loader/epilogue
// amortized, two independent dependency chains per thread.

#define H 512
#define W 512
#define NPLANES 48

#define TILE_W 64
#define TILE_H 16
#define BLK_X 32
#define BLK_Y 8
#define SM_W  68
#define SM_H  20

#define G1f 0.66151464f
#define G2f 0.19149516f

// deg-2 Chebyshev coeffs for exp(-a*u), u in [0,1]
#define Q0 0.99969391f
#define Q1 -0.40757903f
#define Q2 0.06969310f

typedef unsigned long long u64;

__device__ __forceinline__ u64 pk(float lo, float hi) {
    u64 r; asm("mov.b64 %0, {%1, %2};" : "=l"(r) : "f"(lo), "f"(hi)); return r;
}
__device__ __forceinline__ u64 f2add(u64 a, u64 b) {
    u64 d; asm("add.rn.f32x2 %0, %1, %2;" : "=l"(d) : "l"(a), "l"(b)); return d;
}
__device__ __forceinline__ u64 f2sub(u64 a, u64 b) {
    u64 d; asm("sub.rn.f32x2 %0, %1, %2;" : "=l"(d) : "l"(a), "l"(b)); return d;
}
__device__ __forceinline__ u64 f2mul(u64 a, u64 b) {
    u64 d; asm("mul.rn.f32x2 %0, %1, %2;" : "=l"(d) : "l"(a), "l"(b)); return d;
}
__device__ __forceinline__ u64 f2fma(u64 a, u64 b, u64 c) {
    u64 d; asm("fma.rn.f32x2 %0, %1, %2, %3;" : "=l"(d) : "l"(a), "l"(b), "l"(c)); return d;
}
__device__ __forceinline__ void unpk(u64 q, float& lo, float& hi) {
    asm("mov.b64 {%0, %1}, %2;" : "=f"(lo), "=f"(hi) : "l"(q));
}

__device__ __forceinline__ int reflect_idx(int i, int n) {
    if (i < 0)  i = -i;
    if (i >= n) i = 2 * n - 2 - i;
    return i;
}

__global__ __launch_bounds__(BLK_X * BLK_Y, 6)
void bilateral_kernel(const float* __restrict__ in, float* __restrict__ out) {
    // smB[r][c] == smA[r][c+1]  (shifted copy -> odd-offset pairs are aligned LDS.64)
    __shared__ __align__(8) float smA[SM_H][SM_W];
    __shared__ __align__(8) float smB[SM_H][SM_W];

    const int tx = threadIdx.x;
    const int ty = threadIdx.y;
    const int bx = blockIdx.x * TILE_W;
    const int by = blockIdx.y * TILE_H;
    const int pbase = blockIdx.z * (H * W);    // < 2^31, 32-bit safe

    // ---- division-free cooperative tile load (32-bit indexing) ----
    const bool interior = (bx != 0) && (bx != (W - TILE_W)) &&
                          (by != 0) && (by != (H - TILE_H));

    #define STORE_SM(r, c, v)                  \
    {                                          \
        smA[r][c] = (v);                       \
        if ((c) > 0) smB[r][(c) - 1] = (v);    \
    }

    if (interior) {
        const float* src = in + (pbase + (by - 2) * W + (bx - 2));
        #pragma unroll
        for (int rr = 0; rr < 3; rr++) {
            int r = ty + rr * BLK_Y;
            if (r < SM_H) {
                const float* sr = src + r * W;
                #pragma unroll
                for (int cc = 0; cc < 3; cc++) {
                    int c = tx + cc * BLK_X;
                    if (c < SM_W) {
                        float v = sr[c];
                        STORE_SM(r, c, v)
                    }
                }
            }
        }
    } else {
        #pragma unroll
        for (int rr = 0; rr < 3; rr++) {
            int r = ty + rr * BLK_Y;
            if (r < SM_H) {
                int gy = reflect_idx(by - 2 + r, H);
                const float* sr = in + (pbase + gy * W);
                #pragma unroll
                for (int cc = 0; cc < 3; cc++) {
                    int c = tx + cc * BLK_X;
                    if (c < SM_W) {
                        int gx = reflect_idx(bx - 2 + c, W);
                        float v = sr[gx];
                        STORE_SM(r, c, v)
                    }
                }
            }
        }
    }
    #undef STORE_SM
    __syncthreads();

    // horizontally-folded poly coefficient sets: coef = g * {Q2, Q1, Q0}
    const u64 A2 = pk(Q2, Q2);                          // g = 1
    const u64 A1 = pk(Q1, Q1);
    const u64 A0 = pk(Q0, Q0);
    const u64 B2 = pk(0.04610273f, 0.04610273f);        // g = G1
    const u64 B1 = pk(-0.26961989f, -0.26961989f);
    const u64 B0 = pk(0.66131215f, 0.66131215f);
    const u64 E2 = pk(0.01334589f, 0.01334589f);        // g = G2
    const u64 E1 = pk(-0.07804951f, -0.07804951f);
    const u64 E0 = pk(0.19143654f, 0.19143654f);
    const u64 GV1 = pk(G1f, G1f);
    const u64 GV2 = pk(G2f, G2f);

    const int col = 2 * tx;
    const int rb  = 2 * ty;

    const u64 ctrA = *(const u64*)&smA[rb + 2][col + 2];
    const u64 ctrB = *(const u64*)&smA[rb + 3][col + 2];

    u64 numA, denA, numB, denB;

    #define ROWLOAD(r)                                  \
        const float* rA = &smA[rb + (r)][col];          \
        const float* rB = &smB[rb + (r)][col];          \
        u64 p0 = *(const u64*)(rA + 0);                 \
        u64 p1 = *(const u64*)(rB + 0);                 \
        u64 p2 = *(const u64*)(rA + 2);                 \
        u64 p3 = *(const u64*)(rB + 2);                 \
        u64 p4 = *(const u64*)(rA + 4);

    #define TAPW(P, K2, K1, K0, WOUT)                   \
        u64 WOUT;                                       \
        {                                               \
            u64 dd = f2sub((P), ctr);                   \
            u64 uu = f2mul(dd, dd);                     \
            u64 tt = f2fma((K2), uu, (K1));             \
            WOUT = f2fma(tt, uu, (K0));                 \
        }

    // produce row sums rn, rd against center CTR
    #define ROWTAPS(CTR, RN, RD)                        \
        u64 RN, RD;                                     \
        {                                               \
            u64 ctr = (CTR);                            \
            TAPW(p0, E2, E1, E0, w0)                    \
            RD = w0;                                    \
            RN = f2mul(w0, p0);                         \
            TAPW(p1, B2, B1, B0, w1)                    \
            RD = f2add(RD, w1);                         \
            RN = f2fma(w1, p1, RN);                     \
            TAPW(p2, A2, A1, A0, w2)                    \
            RD = f2add(RD, w2);                         \
            RN = f2fma(w2, p2, RN);                     \
            TAPW(p3, B2, B1, B0, w3)                    \
            RD = f2add(RD, w3);                         \
            RN = f2fma(w3, p3, RN);                     \
            TAPW(p4, E2, E1, E0, w4)                    \
            RD = f2add(RD, w4);                         \
            RN = f2fma(w4, p4, RN);                     \
        }

    {   // row 0: A only (vertical weight G2) — init A
        ROWLOAD(0)
        ROWTAPS(ctrA, rn, rd)
        denA = f2mul(GV2, rd);
        numA = f2mul(GV2, rn);
    }
    {   // row 1: A (G1), B (G2, init)
        ROWLOAD(1)
        { ROWTAPS(ctrA, rn, rd)
          denA = f2fma(GV1, rd, denA); numA = f2fma(GV1, rn, numA); }
        { ROWTAPS(ctrB, rn, rd)
          denB = f2mul(GV2, rd);       numB = f2mul(GV2, rn); }
    }
    {   // row 2: A (unit), B (G1)
        ROWLOAD(2)
        { ROWTAPS(ctrA, rn, rd)
          denA = f2add(denA, rd);      numA = f2add(numA, rn); }
        { ROWTAPS(ctrB, rn, rd)
          denB = f2fma(GV1, rd, denB); numB = f2fma(GV1, rn, numB); }
    }
    {   // row 3: A (G1), B (unit)
        ROWLOAD(3)
        { ROWTAPS(ctrA, rn, rd)
          denA = f2fma(GV1, rd, denA); numA = f2fma(GV1, rn, numA); }
        { ROWTAPS(ctrB, rn, rd)
          denB = f2add(denB, rd);      numB = f2add(numB, rn); }
    }
    {   // row 4: A (G2), B (G1)
        ROWLOAD(4)
        { ROWTAPS(ctrA, rn, rd)
          denA = f2fma(GV2, rd, denA); numA = f2fma(GV2, rn, numA); }
        { ROWTAPS(ctrB, rn, rd)
          denB = f2fma(GV1, rd, denB); numB = f2fma(GV1, rn, numB); }
    }
    {   // row 5: B only (G2)
        ROWLOAD(5)
        ROWTAPS(ctrB, rn, rd)
        denB = f2fma(GV2, rd, denB);
        numB = f2fma(GV2, rn, numB);
    }

    #undef ROWTAPS
    #undef TAPW
    #undef ROWLOAD

    float na0, na1, da0, da1, nb0, nb1, db0, db1;
    unpk(numA, na0, na1);
    unpk(denA, da0, da1);
    unpk(numB, nb0, nb1);
    unpk(denB, db0, db1);

    float2 oA, oB;
    oA.x = __fdividef(na0, da0);
    oA.y = __fdividef(na1, da1);
    oB.x = __fdividef(nb0, db0);
    oB.y = __fdividef(nb1, db1);

    float* op = out + (pbase + (by + rb) * W + bx + col);
    *(float2*)op       = oA;
    *(float2*)(op + W) = oB;
}

extern "C" void kernel_launch(void* const* d_in, const int* in_sizes, int n_in,
                              void* d_out, int out_size) {
    const float* x = (const float*)d_in[0];
    float* y = (float*)d_out;
    dim3 block(BLK_X, BLK_Y);
    dim3 grid(W / TILE_W, H / TILE_H, NPLANES);
    bilateral_kernel<<<grid, block>>>(x, y);
}